// round 16
// baseline (speedup 1.0000x reference)
#include <cuda_runtime.h>
#include <math.h>

#define NN 200000
#define NE 3200000
#define NP 4096
#define SCAN_T 1024
#define SCAN_NB 196   // ceil(NN/1024)

// ---------------- scratch (__device__ globals; no allocation) ----------------
__device__ int d_deg[NN];            // invariant: zero at entry (restored by k_scan)
__device__ int d_start[NN];          // segment start per node (arrival-ordered)
__device__ int d_len[NN];            // segment length per node
__device__ int d_cursor[NN];
__device__ int d_gctr;               // global range allocator (zeroed by k_hist)
__device__ int d_ssrc[NE];           // src indices grouped by dst
__device__ float d_mean[NN * 32];    // per-layer aggregated mean scratch

__device__ __forceinline__ float tanh_approx(float v) {
    float r;
    asm("tanh.approx.f32 %0, %1;" : "=f"(r) : "f"(v));
    return r;
}

// ---------------- CSR build: hist -> scan -> scatter (3 launches) ----------------
__global__ void k_hist(const int* __restrict__ dst) {
    if (blockIdx.x == 0 && threadIdx.x == 0) d_gctr = 0;   // consumed next launch
    int e = blockIdx.x * blockDim.x + threadIdx.x;
    if (e < NE) atomicAdd(&d_deg[dst[e]], 1);
}

// Block-local inclusive scan + atomic block-range grab (arrival-ordered across
// blocks; valid since consumers only need disjoint start+len per node).
__global__ void k_scan() {
    __shared__ int s[SCAN_T];
    __shared__ int blockBase;
    int t = threadIdx.x;
    int i = blockIdx.x * SCAN_T + t;
    int v = (i < NN) ? d_deg[i] : 0;
    s[t] = v;
    __syncthreads();
    for (int o = 1; o < SCAN_T; o <<= 1) {
        int tv = (t >= o) ? s[t - o] : 0;
        __syncthreads();
        s[t] += tv;
        __syncthreads();
    }
    if (t == SCAN_T - 1) blockBase = atomicAdd(&d_gctr, s[SCAN_T - 1]);
    __syncthreads();
    if (i < NN) {
        int excl = blockBase + s[t] - v;
        d_start[i]  = excl;
        d_cursor[i] = excl;
        d_len[i]    = v;
        d_deg[i]    = 0;                 // restore zero invariant for next call
    }
}

__global__ void k_scatter(const int* __restrict__ src, const int* __restrict__ dst) {
    int e = blockIdx.x * blockDim.x + threadIdx.x;
    if (e < NE) {
        int p = atomicAdd(&d_cursor[dst[e]], 1);
        d_ssrc[p] = src[e];
    }
}

// ---------------- aggregation: mean of in-neighbors -> d_mean ----------------
// Group-per-node: each 8-lane group owns one node (8 lanes x float4 = 32
// features); warp = 4 nodes. No shuffles at all: idx loads are group-broadcast
// LDG.32 (batched 4/block, predicated), feature loads are batched LDG.128
// (4 rows per warp instruction), next block's indices prefetched during the
// current gather, result stored directly (coalesced 512B per warp).
__global__ void __launch_bounds__(256) k_aggregate(
        const float* __restrict__ hprev, int strideFloats) {
    int tid = threadIdx.x;
    int warp = tid >> 5, lane = tid & 31;
    int grp = lane >> 3;          // node within the warp's quad
    int l8  = lane & 7;           // feature chunk 0..7
    int n = (blockIdx.x * 8 + warp) * 4 + grp;    // exact: NN % 32 == 0

    const char* hbase = (const char*)hprev;
    int rowBytes = strideFloats * 4;
    int off = l8 * 16;

    int st = d_start[n];          // group-broadcast load
    int ln = d_len[n];
    float4 acc = make_float4(0.f, 0.f, 0.f, 0.f);

    // prefetch first 4 indices (predicated, independent -> batched)
    int i0 = 0, i1 = 0, i2 = 0, i3 = 0;
    if (ln > 0) i0 = d_ssrc[st];
    if (ln > 1) i1 = d_ssrc[st + 1];
    if (ln > 2) i2 = d_ssrc[st + 2];
    if (ln > 3) i3 = d_ssrc[st + 3];

    for (int e = 0; e < ln; e += 4) {
        int j0 = i0, j1 = i1, j2 = i2, j3 = i3;
        int rem = ln - e;                      // >= 1
        int en = e + 4;
        if (en < ln) {                         // prefetch next block's indices
            int r2 = ln - en;
            i0 = d_ssrc[st + en];
            i1 = (r2 > 1) ? d_ssrc[st + en + 1] : 0;
            i2 = (r2 > 2) ? d_ssrc[st + en + 2] : 0;
            i3 = (r2 > 3) ? d_ssrc[st + en + 3] : 0;
        }
        float4 p;
        p = *(const float4*)(hbase + (size_t)j0 * rowBytes + off);
        acc.x += p.x; acc.y += p.y; acc.z += p.z; acc.w += p.w;
        if (rem > 1) {
            p = *(const float4*)(hbase + (size_t)j1 * rowBytes + off);
            acc.x += p.x; acc.y += p.y; acc.z += p.z; acc.w += p.w;
        }
        if (rem > 2) {
            p = *(const float4*)(hbase + (size_t)j2 * rowBytes + off);
            acc.x += p.x; acc.y += p.y; acc.z += p.z; acc.w += p.w;
        }
        if (rem > 3) {
            p = *(const float4*)(hbase + (size_t)j3 * rowBytes + off);
            acc.x += p.x; acc.y += p.y; acc.z += p.z; acc.w += p.w;
        }
    }
    float inv = 1.0f / fmaxf((float)ln, 1.0f);
    float4 m = make_float4(acc.x * inv, acc.y * inv, acc.z * inv, acc.w * inv);
    *(float4*)(d_mean + (size_t)n * 32 + l8 * 4) = m;   // coalesced STG.128
}

// ---------------- dense layer: tanh(x@Ws + mean@Wn + b) -> concat slice --------
#define NPW_D 16
__global__ void __launch_bounds__(256) k_dense(
        const float* __restrict__ x, int xstride,
        float* __restrict__ concat, int layer,
        const float* __restrict__ Ws, const float* __restrict__ Wn,
        const float* __restrict__ b) {
    __shared__ float sWs[1024], sWn[1024], sb[32];
    int tid = threadIdx.x;
    for (int i = tid; i < 1024; i += 256) { sWs[i] = Ws[i]; sWn[i] = Wn[i]; }
    if (tid < 32) sb[tid] = b[tid];
    __syncthreads();

    int warp = tid >> 5, lane = tid & 31;
    float wsr[32], wnr[32];
    #pragma unroll
    for (int k = 0; k < 32; k++) {
        wsr[k] = sWs[k * 32 + lane];
        wnr[k] = sWn[k * 32 + lane];
    }
    float bias = sb[lane];

    int wg = blockIdx.x * 8 + warp;
    int n0 = wg * NPW_D;
    #pragma unroll 1
    for (int i = 0; i < NPW_D; i++) {
        int n = n0 + i;
        if (n >= NN) return;
        const float4* xr = (const float4*)(x + (size_t)n * xstride);
        const float4* mr = (const float4*)(d_mean + (size_t)n * 32);
        float rs = bias, rn = 0.f;
        #pragma unroll
        for (int k4 = 0; k4 < 8; k4++) {
            float4 xv = xr[k4];            // broadcast LDG.128
            float4 mv = mr[k4];            // broadcast LDG.128
            rs += xv.x * wsr[4 * k4]     + xv.y * wsr[4 * k4 + 1]
                + xv.z * wsr[4 * k4 + 2] + xv.w * wsr[4 * k4 + 3];
            rn += mv.x * wnr[4 * k4]     + mv.y * wnr[4 * k4 + 1]
                + mv.z * wnr[4 * k4 + 2] + mv.w * wnr[4 * k4 + 3];
        }
        concat[(size_t)n * 128 + layer * 32 + lane] = tanh_approx(rs + rn);
    }
}

// ---------------- pair MLP (r14 form) ----------------
__global__ void k_mlp(const float* __restrict__ concat,
                      const int* __restrict__ uidx, const int* __restrict__ iidx,
                      const float* __restrict__ W1, const float* __restrict__ bl1,
                      const float* __restrict__ W2, const float* __restrict__ bl2,
                      float* __restrict__ score, int pairs_per_block) {
    __shared__ float spair[256];
    __shared__ float sred[4];
    int tid = threadIdx.x;   // 0..127
    float w2 = W2[tid];
    float b1 = bl1[tid];
    float b2 = bl2[0];
    int p0 = blockIdx.x * pairs_per_block;
    int p1 = min(NP, p0 + pairs_per_block);
    for (int p = p0; p < p1; p++) {
        int u = uidx[p], it = iidx[p];
        spair[tid]       = concat[(size_t)u  * 128 + tid];
        spair[128 + tid] = concat[(size_t)it * 128 + tid];
        __syncthreads();
        float acc = b1;
        #pragma unroll 8
        for (int k = 0; k < 256; k++) acc += spair[k] * W1[k * 128 + tid];
        float h = fmaxf(acc, 0.f) * w2;
        #pragma unroll
        for (int o = 16; o > 0; o >>= 1) h += __shfl_down_sync(0xffffffffu, h, o);
        if ((tid & 31) == 0) sred[tid >> 5] = h;
        __syncthreads();
        if (tid == 0) {
            float s = sred[0] + sred[1] + sred[2] + sred[3] + b2;
            score[p] = 1.0f / (1.0f + __expf(-s));
        }
        __syncthreads();
    }
}

// ---------------- launch ----------------
extern "C" void kernel_launch(void* const* d_in, const int* in_sizes, int n_in,
                              void* d_out, int out_size) {
    const float* x    = (const float*)d_in[0];
    const int*   src  = (const int*)d_in[1];
    const int*   dst  = (const int*)d_in[2];
    const int*   uidx = (const int*)d_in[3];
    const int*   iidx = (const int*)d_in[4];
    const float* Ws[4] = { (const float*)d_in[5], (const float*)d_in[8],
                           (const float*)d_in[11], (const float*)d_in[14] };
    const float* Wn[4] = { (const float*)d_in[6], (const float*)d_in[9],
                           (const float*)d_in[12], (const float*)d_in[15] };
    const float* bb[4] = { (const float*)d_in[7], (const float*)d_in[10],
                           (const float*)d_in[13], (const float*)d_in[16] };
    const float* W1  = (const float*)d_in[17];
    const float* bl1 = (const float*)d_in[18];
    const float* W2  = (const float*)d_in[19];
    const float* bl2 = (const float*)d_in[20];

    float* out    = (float*)d_out;
    float* score  = out;              // output 0: [4096]
    float* concat = out + NP;         // output 1: [200000, 128]

    // CSR build (3 launches; launch index 5 = aggregate L1 -> profiled slot)
    k_hist<<<(NE + 255) / 256, 256>>>(dst);
    k_scan<<<SCAN_NB, SCAN_T>>>();
    k_scatter<<<(NE + 255) / 256, 256>>>(src, dst);

    // 4 layers: aggregate (group-per-node gather) + dense (FFMA, reg weights)
    const int AGG_NBLK = NN / 32;                 // 6250, exact
    const int DEN_NBLK = (NN + 8 * NPW_D - 1) / (8 * NPW_D);

    k_aggregate<<<AGG_NBLK, 256>>>(x, 32);
    k_dense<<<DEN_NBLK, 256>>>(x, 32, concat, 0, Ws[0], Wn[0], bb[0]);
    for (int L = 1; L < 4; L++) {
        const float* hin = concat + (L - 1) * 32;
        k_aggregate<<<AGG_NBLK, 256>>>(hin, 128);
        k_dense<<<DEN_NBLK, 256>>>(hin, 128, concat, L, Ws[L], Wn[L], bb[L]);
    }

    // Pair-scoring MLP.
    const int MLP_BLOCKS = 128;
    k_mlp<<<MLP_BLOCKS, 128>>>(concat, uidx, iidx, W1, bl1, W2, bl2, score,
                               NP / MLP_BLOCKS);
}